// round 5
// baseline (speedup 1.0000x reference)
#include <cuda_runtime.h>

#define BSZ 512
#define NN 1000
#define D 128
#define STR 384   // K_att/V_att innermost stride in floats (3 layers * 128)
#define NW 12     // warps per CTA

__device__ __forceinline__ float4 zero4() { return make_float4(0.f, 0.f, 0.f, 0.f); }

// One CTA per batch, 384 threads = 12 warps (41.5 warps/SM resident).
// Warp w owns compacted positions w, w+12, ... with one-node register lookahead.
// Lane t owns floats [4t,4t+4) of the 128-float layer slice.

__global__ __launch_bounds__(384, 4)
void decoder_fused_kernel(
    const float* __restrict__ query,
    const float* __restrict__ K_att,
    const float* __restrict__ V_att,
    const int* __restrict__ mask,          // bool serialized as int32
    const float* __restrict__ W0_w,
    const float* __restrict__ W0_b,
    const float* __restrict__ Wq_w,
    const float* __restrict__ Wq_b,
    float* __restrict__ out)
{
    __shared__ int nlist[NN];
    __shared__ int cnt_s;
    __shared__ __align__(16) float qs[D];
    __shared__ __align__(16) float mo[D];
    __shared__ float m_s[NW][32];
    __shared__ float l_s[NW][32];
    __shared__ __align__(16) float4 a_s[NW][32];
    __shared__ float M2s, L2s;

    const int b = blockIdx.x;
    const int tid = threadIdx.x;
    const int wid = tid >> 5;
    const int lane = tid & 31;
    const int loff = 4 * lane;

    if (tid < D) qs[tid] = query[(size_t)b * D + tid];

    // ---- Compact unmasked node list (warp 0) ----
    const int* mrow = mask + (size_t)b * NN;
    if (wid == 0) {
        int base = 0;
        for (int start = 0; start < NN; start += 32) {
            int n = start + lane;
            bool keep = (n < NN) && (mrow[n] == 0);
            unsigned bal = __ballot_sync(0xffffffffu, keep);
            if (keep) {
                int pos = base + __popc(bal & ((1u << lane) - 1u));
                nlist[pos] = n;
            }
            base += __popc(bal);
        }
        if (lane == 0) cnt_s = base;
    }
    __syncthreads();
    const int cnt = cnt_s;

    const float* Kb = K_att + (size_t)b * NN * STR;
    const float* Vb = V_att + (size_t)b * NN * STR;

    // ==================== Layers 0 and 1: 8-head MHA + W0 linear ====================
    for (int l = 0; l < 2; ++l) {
        const int cbase = l * D + loff;
        const float4 q4 = *(const float4*)(qs + loff);

        float m = -1e30f, lsum = 0.0f;
        float4 acc = zero4();

        int p = wid;
        float4 k4 = zero4(), v4 = zero4();
        if (p < cnt) {
            size_t o = (size_t)nlist[p] * STR + cbase;
            k4 = *(const float4*)(Kb + o);
            v4 = *(const float4*)(Vb + o);
        }
        while (p < cnt) {
            const float4 kc = k4;
            const float4 vc = v4;
            const int pn = p + NW;
            if (pn < cnt) {
                size_t o = (size_t)nlist[pn] * STR + cbase;
                k4 = *(const float4*)(Kb + o);
                v4 = *(const float4*)(Vb + o);
            }
            float s = kc.x * q4.x + kc.y * q4.y + kc.z * q4.z + kc.w * q4.w;
            s += __shfl_xor_sync(0xffffffffu, s, 1);
            s += __shfl_xor_sync(0xffffffffu, s, 2);
            s *= 0.25f;  // 1/sqrt(16)

            const float mn = fmaxf(m, s);
            const float c = __expf(m - mn);
            const float e = __expf(s - mn);
            lsum = lsum * c + e;
            acc.x = acc.x * c + e * vc.x;
            acc.y = acc.y * c + e * vc.y;
            acc.z = acc.z * c + e * vc.z;
            acc.w = acc.w * c + e * vc.w;
            m = mn;
            p = pn;
        }

        m_s[wid][lane] = m;
        l_s[wid][lane] = lsum;
        a_s[wid][lane] = acc;
        __syncthreads();

        // merge the NW warp-partials (lane t of warp 0 merges slot t)
        if (tid < 32) {
            float M = m_s[0][lane];
            #pragma unroll
            for (int w = 1; w < NW; ++w) M = fmaxf(M, m_s[w][lane]);
            float L = 0.f;
            float ax = 0.f, ay = 0.f, az = 0.f, aw = 0.f;
            #pragma unroll
            for (int w = 0; w < NW; ++w) {
                const float c = __expf(m_s[w][lane] - M);
                L += l_s[w][lane] * c;
                const float4 a = a_s[w][lane];
                ax += a.x * c; ay += a.y * c; az += a.z * c; aw += a.w * c;
            }
            const float inv = 1.0f / L;
            mo[4 * lane + 0] = ax * inv;
            mo[4 * lane + 1] = ay * inv;
            mo[4 * lane + 2] = az * inv;
            mo[4 * lane + 3] = aw * inv;
        }
        __syncthreads();

        // query = mha_out @ W0_w.T + W0_b
        if (tid < D) {
            const float* Wr = W0_w + tid * D;
            float a2 = W0_b[tid];
            #pragma unroll 8
            for (int d = 0; d < D; ++d) a2 = fmaf(mo[d], Wr[d], a2);
            qs[tid] = a2;
        }
        __syncthreads();
    }

    // ==================== Layer 2: q_final = q @ Wq.T + b; 1-head, clip=10 ====================
    if (tid < D) {
        const float* Wr = Wq_w + tid * D;
        float a2 = Wq_b[tid];
        #pragma unroll 8
        for (int d = 0; d < D; ++d) a2 = fmaf(qs[d], Wr[d], a2);
        mo[tid] = a2;
    }
    __syncthreads();

    {
        const int cbase = 2 * D + loff;
        const float4 q4 = *(const float4*)(mo + loff);
        float* orow = out + (size_t)b * NN;

        float m = -1e30f, lsum = 0.0f;

        int p = wid;
        float4 k4 = zero4();
        int n0 = 0;
        if (p < cnt) {
            n0 = nlist[p];
            k4 = *(const float4*)(Kb + (size_t)n0 * STR + cbase);
        }
        while (p < cnt) {
            const float4 kc = k4;
            const int n = n0;
            const int pn = p + NW;
            if (pn < cnt) {
                n0 = nlist[pn];
                k4 = *(const float4*)(Kb + (size_t)n0 * STR + cbase);
            }
            float s = kc.x * q4.x + kc.y * q4.y + kc.z * q4.z + kc.w * q4.w;
            #pragma unroll
            for (int d = 1; d < 32; d <<= 1)
                s += __shfl_xor_sync(0xffffffffu, s, d);
            s *= 0.08838834764831845f;           // 1/sqrt(128)
            // 10*tanh(s) = 10*(1 - 2/(exp(2s)+1))
            s = 10.0f * (1.0f - __fdividef(2.0f, __expf(2.0f * s) + 1.0f));

            if (lane == 0) orow[n] = s;          // stage unnormalized logit
            const float mn = fmaxf(m, s);
            lsum = lsum * __expf(m - mn) + __expf(s - mn);
            m = mn;
            p = pn;
        }

        if (lane == 0) { m_s[wid][0] = m; l_s[wid][0] = lsum; }
        __syncthreads();
        if (tid == 0) {
            float M = m_s[0][0];
            #pragma unroll
            for (int w = 1; w < NW; ++w) M = fmaxf(M, m_s[w][0]);
            float L = 0.f;
            #pragma unroll
            for (int w = 0; w < NW; ++w) L += l_s[w][0] * __expf(m_s[w][0] - M);
            M2s = M;
            L2s = 1.0f / L;
        }
        __syncthreads();

        const float M = M2s, Li = L2s;
        for (int n = tid; n < NN; n += 384) {
            float v = 0.0f;
            if (mrow[n] == 0) v = __expf(orow[n] - M) * Li;
            orow[n] = v;
        }
    }
}

extern "C" void kernel_launch(void* const* d_in, const int* in_sizes, int n_in,
                              void* d_out, int out_size) {
    const float* query = (const float*)d_in[0];
    const float* K_att = (const float*)d_in[1];
    const float* V_att = (const float*)d_in[2];
    const int*   mask  = (const int*)d_in[3];
    const float* W0_w  = (const float*)d_in[4];
    const float* W0_b  = (const float*)d_in[5];
    const float* Wq_w  = (const float*)d_in[6];
    const float* Wq_b  = (const float*)d_in[7];
    float* out = (float*)d_out;

    decoder_fused_kernel<<<BSZ, 384>>>(query, K_att, V_att, mask,
                                       W0_w, W0_b, Wq_w, Wq_b, out);
}